// round 1
// baseline (speedup 1.0000x reference)
#include <cuda_runtime.h>
#include <math.h>
#include <stdint.h>

// ---------------------------------------------------------------------------
// Intention_PS_LSTM: 2 encoder LSTMs (speed, pos) + decoder LSTM + fc/emb/softmax
// B=8192, T=16, H=512, F=4, seq_len=16.
//
// Round 0 baseline: fp32 SMEM-tiled fused LSTM-step GEMM.
//   gates[m, g*512+j] = sum_k h[m,k]*Whh[g*512+j,k]  (+ x[m,:4] @ Wih^T + b)
//   Block tile: 128 rows x (32 hidden units x 4 gates = 128 cols), BK=32.
//   Epilogue applies the LSTM cell update in-register: c in-place, h ping-pong.
// ---------------------------------------------------------------------------

#define HID   512
#define F_IN  4
#define BM    128
#define BK    32
#define JT    32
#define MAXB  8192
#define BH    ((size_t)MAXB * HID)

// Scratch (device globals; no allocation allowed)
__device__ __align__(16) float g_h[4 * BH];        // encoder h, slot = ping*2 + z
__device__ __align__(16) float g_c[2 * BH];        // encoder c, slot = z
__device__ __align__(16) float g_hd[2 * BH];       // decoder h ping-pong
__device__ __align__(16) float g_cd[BH];           // decoder c (in-place)
__device__ __align__(16) float g_lastpos[MAXB * F_IN];

__device__ __forceinline__ float sigm_(float x) { return 1.f / (1.f + __expf(-x)); }

// ---------------------------------------------------------------------------
__global__ void zero_kernel()
{
    size_t i = (size_t)blockIdx.x * blockDim.x + threadIdx.x;
    size_t stride = (size_t)gridDim.x * blockDim.x;
    size_t n = 2 * BH;
    for (; i < n; i += stride) { g_h[i] = 0.f; g_c[i] = 0.f; }
}

// ---------------------------------------------------------------------------
struct StepParams {
    const float* xA; const float* xB;   // per-z input (z = blockIdx.z); NULL => g_lastpos
    int x_stride; int x_off;            // x element: x[m*x_stride + x_off + k], k<4
    const float* WihA; const float* WihB;   // [2048,4]
    const float* WhhA; const float* WhhB;   // [2048,512]
    const float* bihA; const float* bihB;
    const float* bhhA; const float* bhhB;
    int ping; int is_dec; int B;
};

__global__ __launch_bounds__(256) void lstm_step_kernel(StepParams p)
{
    const int z = blockIdx.z;
    const float* __restrict__ Wih = z ? p.WihB : p.WihA;
    const float* __restrict__ Whh = z ? p.WhhB : p.WhhA;
    const float* __restrict__ bih = z ? p.bihB : p.bihA;
    const float* __restrict__ bhh = z ? p.bhhB : p.bhhA;
    const float* __restrict__ xin = z ? p.xB : p.xA;

    const float* __restrict__ hin;
    float* __restrict__ hout;
    float* __restrict__ cio;
    if (p.is_dec) {
        hin  = g_hd + (size_t)p.ping * BH;
        hout = g_hd + (size_t)(p.ping ^ 1) * BH;
        cio  = g_cd;
        if (!xin) xin = g_lastpos;
    } else {
        hin  = g_h + (size_t)(p.ping * 2 + z) * BH;
        hout = g_h + (size_t)((p.ping ^ 1) * 2 + z) * BH;
        cio  = g_c + (size_t)z * BH;
    }

    __shared__ float Hs[BK][BM + 1];   // +1 pad: conflict-free transpose stores
    __shared__ float Ws[BK][BM + 1];
    __shared__ float Xs[BM][F_IN];

    const int tid    = threadIdx.x;
    const int m_base = blockIdx.y * BM;
    const int jbase  = blockIdx.x * JT;

    // stage X tile [BM x 4]
    if (tid < BM) {
        const float* xr = xin + (size_t)(m_base + tid) * p.x_stride + p.x_off;
        float4 v = *(const float4*)xr;
        Xs[tid][0] = v.x; Xs[tid][1] = v.y; Xs[tid][2] = v.z; Xs[tid][3] = v.w;
    }

    const int tm = tid >> 4;   // 0..15 -> 8 rows each
    const int tn = tid & 15;   // 0..15 -> 2 hidden units x 4 gates each

    float acc[8][8];
    #pragma unroll
    for (int i = 0; i < 8; i++)
        #pragma unroll
        for (int j = 0; j < 8; j++) acc[i][j] = 0.f;

    for (int k0 = 0; k0 < HID; k0 += BK) {
        // H tile: [BM rows][BK k] transposed into Hs[k][m]
        #pragma unroll
        for (int it = 0; it < 4; it++) {
            int idx = tid * 4 + it * 1024;        // 0..4095
            int row = idx >> 5, kk = idx & 31;
            float4 v = *(const float4*)(hin + (size_t)(m_base + row) * HID + k0 + kk);
            Hs[kk + 0][row] = v.x; Hs[kk + 1][row] = v.y;
            Hs[kk + 2][row] = v.z; Hs[kk + 3][row] = v.w;
        }
        // W tile: col c = g*32 + jl maps to Whh row g*512 + jbase + jl
        #pragma unroll
        for (int it = 0; it < 4; it++) {
            int idx = tid * 4 + it * 1024;
            int c = idx >> 5, kk = idx & 31;
            int g = c >> 5, jl = c & 31;
            int gr = g * HID + jbase + jl;
            float4 v = *(const float4*)(Whh + (size_t)gr * HID + k0 + kk);
            Ws[kk + 0][c] = v.x; Ws[kk + 1][c] = v.y;
            Ws[kk + 2][c] = v.z; Ws[kk + 3][c] = v.w;
        }
        __syncthreads();

        #pragma unroll
        for (int kk = 0; kk < BK; kk++) {
            float a[8], b[8];
            #pragma unroll
            for (int i = 0; i < 8; i++) a[i] = Hs[kk][tm * 8 + i];
            #pragma unroll
            for (int g = 0; g < 4; g++) {
                b[g * 2 + 0] = Ws[kk][g * 32 + tn * 2 + 0];
                b[g * 2 + 1] = Ws[kk][g * 32 + tn * 2 + 1];
            }
            #pragma unroll
            for (int i = 0; i < 8; i++)
                #pragma unroll
                for (int c = 0; c < 8; c++) acc[i][c] += a[i] * b[c];
        }
        __syncthreads();
    }

    // epilogue: bias + rank-4 input projection + LSTM cell update
    float  bsum[4][2];
    float4 wv[4][2];
    #pragma unroll
    for (int g = 0; g < 4; g++)
        #pragma unroll
        for (int e = 0; e < 2; e++) {
            int gr = g * HID + jbase + tn * 2 + e;
            bsum[g][e] = bih[gr] + bhh[gr];
            wv[g][e]   = *(const float4*)(Wih + (size_t)gr * F_IN);
        }

    #pragma unroll
    for (int i = 0; i < 8; i++) {
        int m = m_base + tm * 8 + i;
        float x0 = Xs[tm * 8 + i][0], x1 = Xs[tm * 8 + i][1];
        float x2 = Xs[tm * 8 + i][2], x3 = Xs[tm * 8 + i][3];
        #pragma unroll
        for (int e = 0; e < 2; e++) {
            float vi = acc[i][0 + e] + bsum[0][e] + wv[0][e].x * x0 + wv[0][e].y * x1 + wv[0][e].z * x2 + wv[0][e].w * x3;
            float vf = acc[i][2 + e] + bsum[1][e] + wv[1][e].x * x0 + wv[1][e].y * x1 + wv[1][e].z * x2 + wv[1][e].w * x3;
            float vg = acc[i][4 + e] + bsum[2][e] + wv[2][e].x * x0 + wv[2][e].y * x1 + wv[2][e].z * x2 + wv[2][e].w * x3;
            float vo = acc[i][6 + e] + bsum[3][e] + wv[3][e].x * x0 + wv[3][e].y * x1 + wv[3][e].z * x2 + wv[3][e].w * x3;
            float is_ = sigm_(vi), fs_ = sigm_(vf);
            float gt  = tanhf(vg), os_ = sigm_(vo);
            size_t idx = (size_t)m * HID + jbase + tn * 2 + e;
            float cn = fs_ * cio[idx] + is_ * gt;
            cio[idx]  = cn;
            hout[idx] = os_ * tanhf(cn);
        }
    }
}

// ---------------------------------------------------------------------------
__global__ void combine_kernel(int fp, int n)
{
    int i = blockIdx.x * blockDim.x + threadIdx.x;
    if (i < n) {
        g_hd[i] = g_h[(size_t)(fp * 2 + 0) * BH + i] + g_h[(size_t)(fp * 2 + 1) * BH + i];
        g_cd[i] = g_c[i] + g_c[BH + i];
    }
}

// ---------------------------------------------------------------------------
// Per decoder step: crossing = relu(h @ Wfc^T + bfc)   [B,2]
//                   last_pos = relu(crossing @ Wemb^T + bemb)   [B,4]
//                   probs    = softmax(crossing)  -> out[b, t, :]
__global__ __launch_bounds__(256) void fc_kernel(
    const float* __restrict__ Wfc, const float* __restrict__ bfc,
    const float* __restrict__ Wemb, const float* __restrict__ bemb,
    float* __restrict__ out, int hping, int t, int L, int B)
{
    __shared__ float Wf[2 * HID];
    int tid = threadIdx.x;
    for (int i = tid; i < 2 * HID; i += 256) Wf[i] = Wfc[i];
    __syncthreads();

    int warp = tid >> 5, lane = tid & 31;
    int b = blockIdx.x * 8 + warp;
    if (b >= B) return;

    const float* hr = g_hd + (size_t)hping * BH + (size_t)b * HID;
    float s0 = 0.f, s1 = 0.f;
    #pragma unroll
    for (int k = lane; k < HID; k += 32) {
        float hv = hr[k];
        s0 += hv * Wf[k];
        s1 += hv * Wf[HID + k];
    }
    #pragma unroll
    for (int o = 16; o; o >>= 1) {
        s0 += __shfl_xor_sync(0xFFFFFFFFu, s0, o);
        s1 += __shfl_xor_sync(0xFFFFFFFFu, s1, o);
    }
    if (lane == 0) {
        float c0 = fmaxf(s0 + bfc[0], 0.f);
        float c1 = fmaxf(s1 + bfc[1], 0.f);
        #pragma unroll
        for (int k = 0; k < 4; k++) {
            float lp = fmaxf(c0 * Wemb[k * 2 + 0] + c1 * Wemb[k * 2 + 1] + bemb[k], 0.f);
            g_lastpos[b * 4 + k] = lp;
        }
        float mx = fmaxf(c0, c1);
        float e0 = __expf(c0 - mx), e1 = __expf(c1 - mx);
        float inv = 1.f / (e0 + e1);
        out[(size_t)b * L * 2 + t * 2 + 0] = e0 * inv;
        out[(size_t)b * L * 2 + t * 2 + 1] = e1 * inv;
    }
}

// ---------------------------------------------------------------------------
extern "C" void kernel_launch(void* const* d_in, const int* in_sizes, int n_in,
                              void* d_out, int out_size)
{
    const float* speed = (const float*)d_in[0];
    const float* pos   = (const float*)d_in[1];
    const float* Ws_ih = (const float*)d_in[2];
    const float* Ws_hh = (const float*)d_in[3];
    const float* bs_ih = (const float*)d_in[4];
    const float* bs_hh = (const float*)d_in[5];
    const float* Wp_ih = (const float*)d_in[6];
    const float* Wp_hh = (const float*)d_in[7];
    const float* bp_ih = (const float*)d_in[8];
    const float* bp_hh = (const float*)d_in[9];
    const float* Wd_ih = (const float*)d_in[10];
    const float* Wd_hh = (const float*)d_in[11];
    const float* bd_ih = (const float*)d_in[12];
    const float* bd_hh = (const float*)d_in[13];
    const float* W_fc  = (const float*)d_in[14];
    const float* b_fc  = (const float*)d_in[15];
    const float* W_emb = (const float*)d_in[16];
    const float* b_emb = (const float*)d_in[17];
    float* out = (float*)d_out;

    const int T = 16;
    const int B = in_sizes[0] / (T * F_IN);
    const int L = out_size / (2 * B);

    // zero initial encoder state (h ping-0 slots for both encoders, and c)
    zero_kernel<<<2048, 256>>>();

    // encoders: both run concurrently via gridDim.z = 2
    dim3 gs(HID / JT, B / BM, 2);
    for (int t = 0; t < T; t++) {
        StepParams p;
        p.xA = speed; p.xB = pos;
        p.x_stride = T * F_IN; p.x_off = t * F_IN;
        p.WihA = Ws_ih; p.WihB = Wp_ih;
        p.WhhA = Ws_hh; p.WhhB = Wp_hh;
        p.bihA = bs_ih; p.bihB = bp_ih;
        p.bhhA = bs_hh; p.bhhB = bp_hh;
        p.ping = t & 1; p.is_dec = 0; p.B = B;
        lstm_step_kernel<<<gs, 256>>>(p);
    }

    // combine final encoder states into decoder initial state
    int final_ping = ((T - 1) & 1) ^ 1;   // slot holding the last-written h
    int n = B * HID;
    combine_kernel<<<(n + 255) / 256, 256>>>(final_ping, n);

    // decoder
    dim3 gd(HID / JT, B / BM, 1);
    for (int t = 0; t < L; t++) {
        StepParams p;
        if (t == 0) {
            p.xA = pos; p.xB = pos;
            p.x_stride = T * F_IN; p.x_off = (T - 1) * F_IN;   // pos[:, -1, :]
        } else {
            p.xA = nullptr; p.xB = nullptr;                     // g_lastpos
            p.x_stride = F_IN; p.x_off = 0;
        }
        p.WihA = Wd_ih; p.WihB = Wd_ih;
        p.WhhA = Wd_hh; p.WhhB = Wd_hh;
        p.bihA = bd_ih; p.bihB = bd_ih;
        p.bhhA = bd_hh; p.bhhB = bd_hh;
        p.ping = t & 1; p.is_dec = 1; p.B = B;
        lstm_step_kernel<<<gd, 256>>>(p);

        fc_kernel<<<(B + 7) / 8, 256>>>(W_fc, b_fc, W_emb, b_emb,
                                        out, (t + 1) & 1, t, L, B);
    }
}

// round 3
// speedup vs baseline: 5.3469x; 5.3469x over previous
#include <cuda_runtime.h>
#include <math.h>
#include <stdint.h>

// ---------------------------------------------------------------------------
// Intention_PS_LSTM on GB300 (plain sm_103 target -> mma.sync HMMA path).
// Recurrent GEMM per step: gates[8192,2048] = h[8192,512] @ Whh^T.
// Per CTA: M=256, N=128 (4 gates x 32 hidden units), K=512, tf32 mma.sync.
// LSTM cell update fused in-register in the epilogue.
// ---------------------------------------------------------------------------

#define HID   512
#define F_IN  4
#define MAXB  8192
#define BH    ((size_t)MAXB * HID)

#define SWZ(x) ((x) ^ ((((uint32_t)(x)) >> 3) & 0x70))

// smem byte offsets (all tile bases 1024-aligned)
#define SM_WX     0                    // float4[128]  = 2048
#define SM_BS     2048                 // float[128]   = 512
#define SM_XS     2560                 // float4[256]  = 4096
#define SM_A0     8192                 // 256 x 128B   = 32768
#define SM_A1     40960
#define SM_B0     73728                // 128 x 128B   = 16384
#define SM_B1     90112
#define SM_TOTAL  106496

__device__ __align__(16) float g_h[4 * BH];     // encoder h: slot = ping*2 + z
__device__ __align__(16) float g_c[2 * BH];     // encoder c: slot = z
__device__ __align__(16) float g_hd[2 * BH];    // decoder h ping-pong
__device__ __align__(16) float g_cd[BH];        // decoder c
__device__ __align__(16) float g_lastpos[MAXB * F_IN];

__device__ __forceinline__ float sigm_(float x) { return 1.f / (1.f + __expf(-x)); }

__device__ __forceinline__ uint32_t smem_u32(const void* p) {
    uint32_t a;
    asm("{ .reg .u64 t; cvta.to.shared.u64 t, %1; cvt.u32.u64 %0, t; }" : "=r"(a) : "l"(p));
    return a;
}
__device__ __forceinline__ void cp16(uint32_t s, const void* g) {
    asm volatile("cp.async.cg.shared.global [%0], [%1], 16;" :: "r"(s), "l"(g));
}
#define CP_COMMIT() asm volatile("cp.async.commit_group;" ::: "memory")
#define CP_WAIT1()  asm volatile("cp.async.wait_group 1;" ::: "memory")
#define CP_WAIT0()  asm volatile("cp.async.wait_group 0;" ::: "memory")

__device__ __forceinline__ void ldsm4(uint32_t* r, uint32_t addr) {
    asm volatile("ldmatrix.sync.aligned.m8n8.x4.shared.b16 {%0,%1,%2,%3}, [%4];"
                 : "=r"(r[0]), "=r"(r[1]), "=r"(r[2]), "=r"(r[3]) : "r"(addr));
}
__device__ __forceinline__ void mma_tf32(float* d, const uint32_t* a, const uint32_t* b) {
    asm volatile("mma.sync.aligned.m16n8k8.row.col.f32.tf32.tf32.f32 "
                 "{%0,%1,%2,%3}, {%4,%5,%6,%7}, {%8,%9}, {%0,%1,%2,%3};"
                 : "+f"(d[0]), "+f"(d[1]), "+f"(d[2]), "+f"(d[3])
                 : "r"(a[0]), "r"(a[1]), "r"(a[2]), "r"(a[3]), "r"(b[0]), "r"(b[1]));
}

// ---------------------------------------------------------------------------
__global__ void zero_kernel()
{
    size_t i = (size_t)blockIdx.x * blockDim.x + threadIdx.x;
    size_t stride = (size_t)gridDim.x * blockDim.x;
    for (size_t n = 2 * BH; i < n; i += stride) { g_h[i] = 0.f; g_c[i] = 0.f; }
}

// ---------------------------------------------------------------------------
struct StepParams {
    const float* xA; const float* xB;   // per-z input; NULL => g_lastpos
    int x_stride; int x_off;
    const float* WihA; const float* WihB;
    const float* WhhA; const float* WhhB;
    const float* bihA; const float* bihB;
    const float* bhhA; const float* bhhB;
    int ping; int is_dec;
};

__device__ __forceinline__ void load_chunk(uint32_t Ab, uint32_t Bb,
                                           const float* __restrict__ hin,
                                           const float* __restrict__ Whh,
                                           int m_base, int jbase, int kf, int tid)
{
    #pragma unroll
    for (int it = 0; it < 4; it++) {                    // A: 256 rows x 8 x 16B
        int idx = tid + it * 512;
        int row = idx >> 3, c16 = idx & 7;
        cp16(Ab + SWZ(row * 128 + c16 * 16),
             hin + (size_t)(m_base + row) * HID + kf + c16 * 4);
    }
    #pragma unroll
    for (int it = 0; it < 2; it++) {                    // B: 128 rows x 8 x 16B
        int idx = tid + it * 512;
        int row = idx >> 3, c16 = idx & 7;
        int g = row >> 5, jj = row & 31;
        cp16(Bb + SWZ(row * 128 + c16 * 16),
             Whh + (size_t)(g * HID + jbase + jj) * HID + kf + c16 * 4);
    }
}

__global__ __launch_bounds__(512, 1) void lstm_mma_step(StepParams p)
{
    extern __shared__ char smem[];
    const uint32_t sb = smem_u32(smem);
    const int tid  = threadIdx.x;
    const int wid  = tid >> 5, lane = tid & 31;
    const int z    = blockIdx.z;
    const int warp_m = wid & 3;        // 4 m-groups of 64 rows
    const int warp_n = wid >> 2;       // 4 n-groups of 8 units (per gate)

    const float* __restrict__ Wih = z ? p.WihB : p.WihA;
    const float* __restrict__ Whh = z ? p.WhhB : p.WhhA;
    const float* __restrict__ bih = z ? p.bihB : p.bihA;
    const float* __restrict__ bhh = z ? p.bhhB : p.bhhA;
    const float* __restrict__ xin = z ? p.xB : p.xA;

    const float* __restrict__ hin;
    float* __restrict__ hout;
    float* __restrict__ cio;
    if (p.is_dec) {
        hin  = g_hd + (size_t)p.ping * BH;
        hout = g_hd + (size_t)(p.ping ^ 1) * BH;
        cio  = g_cd;
        if (!xin) xin = g_lastpos;
    } else {
        hin  = g_h + (size_t)(p.ping * 2 + z) * BH;
        hout = g_h + (size_t)((p.ping ^ 1) * 2 + z) * BH;
        cio  = g_c + (size_t)z * BH;
    }

    const int m_base = blockIdx.y * 256;
    const int jbase  = blockIdx.x * 32;

    float4* Wx = (float4*)(smem + SM_WX);
    float*  Bs = (float*)(smem + SM_BS);
    float4* Xs = (float4*)(smem + SM_XS);

    // stage bias + Wih + x
    if (tid < 128) {
        int g = tid >> 5, u = tid & 31;
        int gr = g * HID + jbase + u;
        Bs[tid] = bih[gr] + bhh[gr];
        Wx[tid] = *(const float4*)(Wih + (size_t)gr * F_IN);
    } else if (tid < 384) {
        int r = tid - 128;
        Xs[r] = *(const float4*)(xin + (size_t)(m_base + r) * p.x_stride + p.x_off);
    }

    // ldmatrix lane addressing (precompute swizzle-invariant parts)
    const int perm  = (lane & 7) << 4;
    const int arow  = warp_m * 64 + (lane & 7) + ((lane >> 3) & 1) * 8;   // + mt*16
    const int koffA = ((lane >> 4) & 1) << 4;                             // + q*32
    const int brow0 = ((lane >> 4) & 1) * 32 + warp_n * 8 + (lane & 7);   // gates 0/1
    const int koffB = ((lane >> 3) & 1) << 4;

    float acc[4][4][4];   // [mt][gate][c]
    #pragma unroll
    for (int mt = 0; mt < 4; mt++)
        #pragma unroll
        for (int g = 0; g < 4; g++)
            #pragma unroll
            for (int c = 0; c < 4; c++) acc[mt][g][c] = 0.f;

    // prologue: prefetch chunks 0,1
    load_chunk(sb + SM_A0, sb + SM_B0, hin, Whh, m_base, jbase, 0, tid);  CP_COMMIT();
    load_chunk(sb + SM_A1, sb + SM_B1, hin, Whh, m_base, jbase, 32, tid); CP_COMMIT();

    for (int kc = 0; kc < 16; kc++) {
        if (kc == 15) { CP_WAIT0(); } else { CP_WAIT1(); }
        __syncthreads();

        const uint32_t Ab = sb + ((kc & 1) ? SM_A1 : SM_A0);
        const uint32_t Bb = sb + ((kc & 1) ? SM_B1 : SM_B0);

        #pragma unroll
        for (int q = 0; q < 4; q++) {
            const int kq4 = q * 32;
            uint32_t af[4][4];
            #pragma unroll
            for (int mt = 0; mt < 4; mt++)
                ldsm4(af[mt], Ab + (arow + mt * 16) * 128 + ((kq4 + koffA) ^ perm));

            uint32_t bf[4][2];
            {
                uint32_t r[4];
                ldsm4(r, Bb + brow0 * 128 + ((kq4 + koffB) ^ perm));
                bf[0][0] = r[0]; bf[0][1] = r[1]; bf[1][0] = r[2]; bf[1][1] = r[3];
                ldsm4(r, Bb + (brow0 + 64) * 128 + ((kq4 + koffB) ^ perm));
                bf[2][0] = r[0]; bf[2][1] = r[1]; bf[3][0] = r[2]; bf[3][1] = r[3];
            }
            #pragma unroll
            for (int mt = 0; mt < 4; mt++)
                #pragma unroll
                for (int g = 0; g < 4; g++)
                    mma_tf32(acc[mt][g], af[mt], bf[g]);
        }
        __syncthreads();
        if (kc + 2 < 16) {
            load_chunk(Ab, Bb, hin, Whh, m_base, jbase, (kc + 2) * 32, tid);
            CP_COMMIT();
        }
    }

    // ---------------- fused epilogue (all in-register per thread) ----------
    const int l2 = lane >> 2;                       // row offset 0..7
    const int u0 = warp_n * 8 + (lane & 3) * 2;     // unit pair base (0..31)

    #pragma unroll
    for (int mt = 0; mt < 4; mt++) {
        #pragma unroll
        for (int rh = 0; rh < 2; rh++) {
            const int mloc = warp_m * 64 + mt * 16 + l2 + rh * 8;
            const int m = m_base + mloc;
            const float4 xv = Xs[mloc];
            const size_t base = (size_t)m * HID + jbase + u0;
            const float2 cold = *(const float2*)(cio + base);
            float hn[2], cn[2];
            #pragma unroll
            for (int e = 0; e < 2; e++) {
                const int u = u0 + e;
                const int ci = rh * 2 + e;
                float4 wi = Wx[u], wf = Wx[32 + u], wg = Wx[64 + u], wo = Wx[96 + u];
                float pi = acc[mt][0][ci] + Bs[u]      + wi.x*xv.x + wi.y*xv.y + wi.z*xv.z + wi.w*xv.w;
                float pf = acc[mt][1][ci] + Bs[32 + u] + wf.x*xv.x + wf.y*xv.y + wf.z*xv.z + wf.w*xv.w;
                float pg = acc[mt][2][ci] + Bs[64 + u] + wg.x*xv.x + wg.y*xv.y + wg.z*xv.z + wg.w*xv.w;
                float po = acc[mt][3][ci] + Bs[96 + u] + wo.x*xv.x + wo.y*xv.y + wo.z*xv.z + wo.w*xv.w;
                float ig = sigm_(pi), fg = sigm_(pf);
                float gg = tanhf(pg), og = sigm_(po);
                float cc = fg * ((e == 0) ? cold.x : cold.y) + ig * gg;
                cn[e] = cc;
                hn[e] = og * tanhf(cc);
            }
            *(float2*)(cio + base)  = make_float2(cn[0], cn[1]);
            *(float2*)(hout + base) = make_float2(hn[0], hn[1]);
        }
    }
}

// ---------------------------------------------------------------------------
__global__ void combine_kernel(int fp, int n)
{
    int i = blockIdx.x * blockDim.x + threadIdx.x;
    if (i < n) {
        g_hd[i] = g_h[(size_t)(fp * 2 + 0) * BH + i] + g_h[(size_t)(fp * 2 + 1) * BH + i];
        g_cd[i] = g_c[i] + g_c[BH + i];
    }
}

// ---------------------------------------------------------------------------
__global__ __launch_bounds__(256) void fc_kernel(
    const float* __restrict__ Wfc, const float* __restrict__ bfc,
    const float* __restrict__ Wemb, const float* __restrict__ bemb,
    float* __restrict__ out, int hping, int t, int L, int B)
{
    __shared__ float Wf[2 * HID];
    int tid = threadIdx.x;
    for (int i = tid; i < 2 * HID; i += 256) Wf[i] = Wfc[i];
    __syncthreads();

    int warp = tid >> 5, lane = tid & 31;
    int b = blockIdx.x * 8 + warp;
    if (b >= B) return;

    const float* hr = g_hd + (size_t)hping * BH + (size_t)b * HID;
    float s0 = 0.f, s1 = 0.f;
    #pragma unroll
    for (int k = lane; k < HID; k += 32) {
        float hv = hr[k];
        s0 += hv * Wf[k];
        s1 += hv * Wf[HID + k];
    }
    #pragma unroll
    for (int o = 16; o; o >>= 1) {
        s0 += __shfl_xor_sync(0xFFFFFFFFu, s0, o);
        s1 += __shfl_xor_sync(0xFFFFFFFFu, s1, o);
    }
    if (lane == 0) {
        float c0 = fmaxf(s0 + bfc[0], 0.f);
        float c1 = fmaxf(s1 + bfc[1], 0.f);
        #pragma unroll
        for (int k = 0; k < 4; k++)
            g_lastpos[b * 4 + k] = fmaxf(c0 * Wemb[k * 2 + 0] + c1 * Wemb[k * 2 + 1] + bemb[k], 0.f);
        float mx = fmaxf(c0, c1);
        float e0 = __expf(c0 - mx), e1 = __expf(c1 - mx);
        float inv = 1.f / (e0 + e1);
        out[(size_t)b * L * 2 + t * 2 + 0] = e0 * inv;
        out[(size_t)b * L * 2 + t * 2 + 1] = e1 * inv;
    }
}

// ---------------------------------------------------------------------------
extern "C" void kernel_launch(void* const* d_in, const int* in_sizes, int n_in,
                              void* d_out, int out_size)
{
    const float* speed = (const float*)d_in[0];
    const float* pos   = (const float*)d_in[1];
    const float* Ws_ih = (const float*)d_in[2];
    const float* Ws_hh = (const float*)d_in[3];
    const float* bs_ih = (const float*)d_in[4];
    const float* bs_hh = (const float*)d_in[5];
    const float* Wp_ih = (const float*)d_in[6];
    const float* Wp_hh = (const float*)d_in[7];
    const float* bp_ih = (const float*)d_in[8];
    const float* bp_hh = (const float*)d_in[9];
    const float* Wd_ih = (const float*)d_in[10];
    const float* Wd_hh = (const float*)d_in[11];
    const float* bd_ih = (const float*)d_in[12];
    const float* bd_hh = (const float*)d_in[13];
    const float* W_fc  = (const float*)d_in[14];
    const float* b_fc  = (const float*)d_in[15];
    const float* W_emb = (const float*)d_in[16];
    const float* b_emb = (const float*)d_in[17];
    float* out = (float*)d_out;

    const int T = 16;
    const int B = in_sizes[0] / (T * F_IN);
    const int L = out_size / (2 * B);

    static int smem_set = 0;
    if (!smem_set) {
        cudaFuncSetAttribute(lstm_mma_step, cudaFuncAttributeMaxDynamicSharedMemorySize, SM_TOTAL);
        smem_set = 1;
    }

    zero_kernel<<<2048, 256>>>();

    dim3 gs(HID / 32, B / 256, 2);
    for (int t = 0; t < T; t++) {
        StepParams p;
        p.xA = speed; p.xB = pos;
        p.x_stride = T * F_IN; p.x_off = t * F_IN;
        p.WihA = Ws_ih; p.WihB = Wp_ih;
        p.WhhA = Ws_hh; p.WhhB = Wp_hh;
        p.bihA = bs_ih; p.bihB = bp_ih;
        p.bhhA = bs_hh; p.bhhB = bp_hh;
        p.ping = t & 1; p.is_dec = 0;
        lstm_mma_step<<<gs, 512, SM_TOTAL>>>(p);
    }

    int final_ping = ((T - 1) & 1) ^ 1;
    int n = B * HID;
    combine_kernel<<<(n + 255) / 256, 256>>>(final_ping, n);

    dim3 gd(HID / 32, B / 256, 1);
    for (int t = 0; t < L; t++) {
        StepParams p;
        if (t == 0) {
            p.xA = pos; p.xB = pos;
            p.x_stride = T * F_IN; p.x_off = (T - 1) * F_IN;
        } else {
            p.xA = nullptr; p.xB = nullptr;
            p.x_stride = F_IN; p.x_off = 0;
        }
        p.WihA = Wd_ih; p.WihB = Wd_ih;
        p.WhhA = Wd_hh; p.WhhB = Wd_hh;
        p.bihA = bd_ih; p.bihB = bd_ih;
        p.bhhA = bd_hh; p.bhhB = bd_hh;
        p.ping = t & 1; p.is_dec = 1;
        lstm_mma_step<<<gd, 512, SM_TOTAL>>>(p);

        fc_kernel<<<(B + 7) / 8, 256>>>(W_fc, b_fc, W_emb, b_emb,
                                        out, (t + 1) & 1, t, L, B);
    }
}

// round 4
// speedup vs baseline: 9.2011x; 1.7208x over previous
#include <cuda_runtime.h>
#include <cuda_bf16.h>
#include <math.h>
#include <stdint.h>

// ---------------------------------------------------------------------------
// Intention_PS_LSTM on GB300 (sm_103 target -> mma.sync bf16 HMMA path).
// gates[8192,2048] = h[8192,512] @ Whh^T, per CTA: M=256, N=128(4g x 32u), K=512.
// bf16 weights/h (pre-converted), fp32 accum + fp32 cell state.
// 3-stage cp.async pipeline, one barrier per K=64 chunk.
// ---------------------------------------------------------------------------

#define HID   512
#define F_IN  4
#define MAXB  8192
#define BH    ((size_t)MAXB * HID)
#define WSZ   (4 * HID * HID)          // one Whh: 2048*512

#define SWZ(x) ((x) ^ ((((uint32_t)(x)) >> 3) & 0x70))

// smem byte offsets
#define SM_WX     0                    // float4[128]  = 2048
#define SM_BS     2048                 // float[128]   = 512
#define SM_XS     2560                 // float4[256]  = 4096
#define SM_A(s)   (8192 + (s) * 32768)     // 256 x 128B per stage
#define SM_B(s)   (106496 + (s) * 16384)   // 128 x 128B per stage
#define SM_TOTAL  155648

__device__ __align__(16) __nv_bfloat16 g_wb[3 * WSZ];   // bf16 Whh: s,p,d
__device__ __align__(16) __nv_bfloat16 g_h[4 * BH];     // encoder h: ping*2+z
__device__ __align__(16) float         g_c[2 * BH];     // encoder c: z
__device__ __align__(16) __nv_bfloat16 g_hd[2 * BH];    // decoder h ping-pong
__device__ __align__(16) float         g_cd[BH];        // decoder c
__device__ __align__(16) float         g_lastpos[MAXB * F_IN];

__device__ __forceinline__ float sigm_(float x) { return 1.f / (1.f + __expf(-x)); }

__device__ __forceinline__ uint32_t smem_u32(const void* p) {
    uint32_t a;
    asm("{ .reg .u64 t; cvta.to.shared.u64 t, %1; cvt.u32.u64 %0, t; }" : "=r"(a) : "l"(p));
    return a;
}
__device__ __forceinline__ void cp16(uint32_t s, const void* g) {
    asm volatile("cp.async.cg.shared.global [%0], [%1], 16;" :: "r"(s), "l"(g));
}
#define CP_COMMIT() asm volatile("cp.async.commit_group;" ::: "memory")
#define CP_WAIT1()  asm volatile("cp.async.wait_group 1;" ::: "memory")
#define CP_WAIT0()  asm volatile("cp.async.wait_group 0;" ::: "memory")

__device__ __forceinline__ void ldsm4(uint32_t* r, uint32_t addr) {
    asm volatile("ldmatrix.sync.aligned.m8n8.x4.shared.b16 {%0,%1,%2,%3}, [%4];"
                 : "=r"(r[0]), "=r"(r[1]), "=r"(r[2]), "=r"(r[3]) : "r"(addr));
}
__device__ __forceinline__ void mma_bf16(float* d, const uint32_t* a, const uint32_t* b) {
    asm volatile("mma.sync.aligned.m16n8k16.row.col.f32.bf16.bf16.f32 "
                 "{%0,%1,%2,%3}, {%4,%5,%6,%7}, {%8,%9}, {%0,%1,%2,%3};"
                 : "+f"(d[0]), "+f"(d[1]), "+f"(d[2]), "+f"(d[3])
                 : "r"(a[0]), "r"(a[1]), "r"(a[2]), "r"(a[3]), "r"(b[0]), "r"(b[1]));
}

// ---------------------------------------------------------------------------
__global__ void init_kernel(const float* __restrict__ ws,
                            const float* __restrict__ wp,
                            const float* __restrict__ wd)
{
    size_t i = (size_t)blockIdx.x * blockDim.x + threadIdx.x;
    size_t stride = (size_t)gridDim.x * blockDim.x;
    for (size_t k = i; k < 3 * (size_t)WSZ; k += stride) {
        size_t w = k / WSZ, r = k % WSZ;
        const float* src = (w == 0) ? ws : (w == 1) ? wp : wd;
        g_wb[k] = __float2bfloat16(src[r]);
    }
    for (size_t k = i; k < 2 * BH; k += stride) {
        g_h[k] = __float2bfloat16(0.f);
        g_c[k] = 0.f;
    }
}

// ---------------------------------------------------------------------------
struct StepParams {
    const float* xA; const float* xB;   // per-z input; NULL => g_lastpos
    int x_stride; int x_off;
    const float* WihA; const float* WihB;
    const float* bihA; const float* bihB;
    const float* bhhA; const float* bhhB;
    int wsel;                           // Whh index base: encoder 0 (z adds), decoder 2
    int ping; int is_dec;
};

__device__ __forceinline__ void load_chunk(uint32_t Ab, uint32_t Bb,
                                           const __nv_bfloat16* __restrict__ hin,
                                           const __nv_bfloat16* __restrict__ Whh,
                                           int m_base, int jbase, int kf, int tid)
{
    #pragma unroll
    for (int it = 0; it < 4; it++) {                    // A: 256 rows x 8 x 16B
        int idx = tid + it * 512;
        int row = idx >> 3, c16 = idx & 7;
        cp16(Ab + SWZ(row * 128 + c16 * 16),
             hin + (size_t)(m_base + row) * HID + kf + c16 * 8);
    }
    #pragma unroll
    for (int it = 0; it < 2; it++) {                    // B: 128 rows x 8 x 16B
        int idx = tid + it * 512;
        int row = idx >> 3, c16 = idx & 7;
        int g = row >> 5, jj = row & 31;
        cp16(Bb + SWZ(row * 128 + c16 * 16),
             Whh + (size_t)(g * HID + jbase + jj) * HID + kf + c16 * 8);
    }
}

__global__ __launch_bounds__(512, 1) void lstm_mma_step(StepParams p)
{
    extern __shared__ char smem[];
    const uint32_t sb = smem_u32(smem);
    const int tid  = threadIdx.x;
    const int wid  = tid >> 5, lane = tid & 31;
    const int z    = blockIdx.z;
    const int warp_m = wid & 3;        // 4 m-groups of 64 rows
    const int warp_n = wid >> 2;       // 4 n-groups of 8 units

    const float* __restrict__ Wih = z ? p.WihB : p.WihA;
    const float* __restrict__ bih = z ? p.bihB : p.bihA;
    const float* __restrict__ bhh = z ? p.bhhB : p.bhhA;
    const float* __restrict__ xin = z ? p.xB : p.xA;
    const __nv_bfloat16* __restrict__ Whh = g_wb + (size_t)(p.wsel + z) * WSZ;

    const __nv_bfloat16* __restrict__ hin;
    __nv_bfloat16* __restrict__ hout;
    float* __restrict__ cio;
    if (p.is_dec) {
        hin  = g_hd + (size_t)p.ping * BH;
        hout = g_hd + (size_t)(p.ping ^ 1) * BH;
        cio  = g_cd;
        if (!xin) xin = g_lastpos;
    } else {
        hin  = g_h + (size_t)(p.ping * 2 + z) * BH;
        hout = g_h + (size_t)((p.ping ^ 1) * 2 + z) * BH;
        cio  = g_c + (size_t)z * BH;
    }

    const int m_base = blockIdx.y * 256;
    const int jbase  = blockIdx.x * 32;

    float4* Wx = (float4*)(smem + SM_WX);
    float*  Bs = (float*)(smem + SM_BS);
    float4* Xs = (float4*)(smem + SM_XS);

    if (tid < 128) {
        int g = tid >> 5, u = tid & 31;
        int gr = g * HID + jbase + u;
        Bs[tid] = bih[gr] + bhh[gr];
        Wx[tid] = *(const float4*)(Wih + (size_t)gr * F_IN);
    } else if (tid < 384) {
        int r = tid - 128;
        Xs[r] = *(const float4*)(xin + (size_t)(m_base + r) * p.x_stride + p.x_off);
    }

    // ldmatrix lane addressing
    const int perm  = (lane & 7) << 4;
    const int arow  = warp_m * 64 + (lane & 7) + ((lane >> 3) & 1) * 8;   // + mt*16
    const int koffA = ((lane >> 4) & 1) << 4;                             // + q*32
    const int brow0 = ((lane >> 4) & 1) * 32 + warp_n * 8 + (lane & 7);   // gates 0/1
    const int koffB = ((lane >> 3) & 1) << 4;

    float acc[4][4][4];   // [mt][gate][c]
    #pragma unroll
    for (int mt = 0; mt < 4; mt++)
        #pragma unroll
        for (int g = 0; g < 4; g++)
            #pragma unroll
            for (int c = 0; c < 4; c++) acc[mt][g][c] = 0.f;

    // prologue: prefetch chunks 0,1 into stages 0,1
    load_chunk(sb + SM_A(0), sb + SM_B(0), hin, Whh, m_base, jbase, 0, tid);  CP_COMMIT();
    load_chunk(sb + SM_A(1), sb + SM_B(1), hin, Whh, m_base, jbase, 64, tid); CP_COMMIT();

    for (int kc = 0; kc < 8; kc++) {
        if (kc == 7) { CP_WAIT0(); } else { CP_WAIT1(); }
        __syncthreads();

        // prefetch chunk kc+2 into the stage freed at the barrier above
        if (kc + 2 < 8) {
            int s = (kc + 2) % 3;
            load_chunk(sb + SM_A(s), sb + SM_B(s), hin, Whh,
                       m_base, jbase, (kc + 2) * 64, tid);
            CP_COMMIT();
        }

        const uint32_t Ab = sb + SM_A(kc % 3);
        const uint32_t Bb = sb + SM_B(kc % 3);

        #pragma unroll
        for (int q = 0; q < 4; q++) {            // 4 x k16 per chunk
            const int kq = q * 32;
            uint32_t af[4][4];
            #pragma unroll
            for (int mt = 0; mt < 4; mt++)
                ldsm4(af[mt], Ab + (arow + mt * 16) * 128 + ((kq + koffA) ^ perm));

            uint32_t bf[4][2];
            {
                uint32_t r[4];
                ldsm4(r, Bb + brow0 * 128 + ((kq + koffB) ^ perm));
                bf[0][0] = r[0]; bf[0][1] = r[1]; bf[1][0] = r[2]; bf[1][1] = r[3];
                ldsm4(r, Bb + (brow0 + 64) * 128 + ((kq + koffB) ^ perm));
                bf[2][0] = r[0]; bf[2][1] = r[1]; bf[3][0] = r[2]; bf[3][1] = r[3];
            }
            #pragma unroll
            for (int mt = 0; mt < 4; mt++)
                #pragma unroll
                for (int g = 0; g < 4; g++)
                    mma_bf16(acc[mt][g], af[mt], bf[g]);
        }
    }

    // ---------------- fused epilogue ----------------
    const int l2 = lane >> 2;
    const int u0 = warp_n * 8 + (lane & 3) * 2;

    #pragma unroll
    for (int mt = 0; mt < 4; mt++) {
        #pragma unroll
        for (int rh = 0; rh < 2; rh++) {
            const int mloc = warp_m * 64 + mt * 16 + l2 + rh * 8;
            const int m = m_base + mloc;
            const float4 xv = Xs[mloc];
            const size_t base = (size_t)m * HID + jbase + u0;
            const float2 cold = *(const float2*)(cio + base);
            float hn[2], cn[2];
            #pragma unroll
            for (int e = 0; e < 2; e++) {
                const int u = u0 + e;
                const int ci = rh * 2 + e;
                float4 wi = Wx[u], wf = Wx[32 + u], wg = Wx[64 + u], wo = Wx[96 + u];
                float pi = acc[mt][0][ci] + Bs[u]      + wi.x*xv.x + wi.y*xv.y + wi.z*xv.z + wi.w*xv.w;
                float pf = acc[mt][1][ci] + Bs[32 + u] + wf.x*xv.x + wf.y*xv.y + wf.z*xv.z + wf.w*xv.w;
                float pg = acc[mt][2][ci] + Bs[64 + u] + wg.x*xv.x + wg.y*xv.y + wg.z*xv.z + wg.w*xv.w;
                float po = acc[mt][3][ci] + Bs[96 + u] + wo.x*xv.x + wo.y*xv.y + wo.z*xv.z + wo.w*xv.w;
                float ig = sigm_(pi), fg = sigm_(pf);
                float gg = tanhf(pg), og = sigm_(po);
                float cc = fg * ((e == 0) ? cold.x : cold.y) + ig * gg;
                cn[e] = cc;
                hn[e] = og * tanhf(cc);
            }
            *(float2*)(cio + base) = make_float2(cn[0], cn[1]);
            *(__nv_bfloat162*)(hout + base) =
                __nv_bfloat162(__float2bfloat16(hn[0]), __float2bfloat16(hn[1]));
        }
    }
}

// ---------------------------------------------------------------------------
__global__ void combine_kernel(int fp, int n)
{
    int i = blockIdx.x * blockDim.x + threadIdx.x;
    if (i < n) {
        float ha = __bfloat162float(g_h[(size_t)(fp * 2 + 0) * BH + i]);
        float hb = __bfloat162float(g_h[(size_t)(fp * 2 + 1) * BH + i]);
        g_hd[i] = __float2bfloat16(ha + hb);
        g_cd[i] = g_c[i] + g_c[BH + i];
    }
}

// ---------------------------------------------------------------------------
__global__ __launch_bounds__(256) void fc_kernel(
    const float* __restrict__ Wfc, const float* __restrict__ bfc,
    const float* __restrict__ Wemb, const float* __restrict__ bemb,
    float* __restrict__ out, int hping, int t, int L, int B)
{
    __shared__ float Wf[2 * HID];
    int tid = threadIdx.x;
    for (int i = tid; i < 2 * HID; i += 256) Wf[i] = Wfc[i];
    __syncthreads();

    int warp = tid >> 5, lane = tid & 31;
    int b = blockIdx.x * 8 + warp;
    if (b >= B) return;

    const __nv_bfloat16* hr = g_hd + (size_t)hping * BH + (size_t)b * HID;
    float s0 = 0.f, s1 = 0.f;
    #pragma unroll
    for (int k = lane; k < HID; k += 32) {
        float hv = __bfloat162float(hr[k]);
        s0 += hv * Wf[k];
        s1 += hv * Wf[HID + k];
    }
    #pragma unroll
    for (int o = 16; o; o >>= 1) {
        s0 += __shfl_xor_sync(0xFFFFFFFFu, s0, o);
        s1 += __shfl_xor_sync(0xFFFFFFFFu, s1, o);
    }
    if (lane == 0) {
        float c0 = fmaxf(s0 + bfc[0], 0.f);
        float c1 = fmaxf(s1 + bfc[1], 0.f);
        #pragma unroll
        for (int k = 0; k < 4; k++)
            g_lastpos[b * 4 + k] = fmaxf(c0 * Wemb[k * 2 + 0] + c1 * Wemb[k * 2 + 1] + bemb[k], 0.f);
        float mx = fmaxf(c0, c1);
        float e0 = __expf(c0 - mx), e1 = __expf(c1 - mx);
        float inv = 1.f / (e0 + e1);
        out[(size_t)b * L * 2 + t * 2 + 0] = e0 * inv;
        out[(size_t)b * L * 2 + t * 2 + 1] = e1 * inv;
    }
}

// ---------------------------------------------------------------------------
extern "C" void kernel_launch(void* const* d_in, const int* in_sizes, int n_in,
                              void* d_out, int out_size)
{
    const float* speed = (const float*)d_in[0];
    const float* pos   = (const float*)d_in[1];
    const float* Ws_ih = (const float*)d_in[2];
    const float* Ws_hh = (const float*)d_in[3];
    const float* bs_ih = (const float*)d_in[4];
    const float* bs_hh = (const float*)d_in[5];
    const float* Wp_ih = (const float*)d_in[6];
    const float* Wp_hh = (const float*)d_in[7];
    const float* bp_ih = (const float*)d_in[8];
    const float* bp_hh = (const float*)d_in[9];
    const float* Wd_ih = (const float*)d_in[10];
    const float* Wd_hh = (const float*)d_in[11];
    const float* bd_ih = (const float*)d_in[12];
    const float* bd_hh = (const float*)d_in[13];
    const float* W_fc  = (const float*)d_in[14];
    const float* b_fc  = (const float*)d_in[15];
    const float* W_emb = (const float*)d_in[16];
    const float* b_emb = (const float*)d_in[17];
    float* out = (float*)d_out;

    const int T = 16;
    const int B = in_sizes[0] / (T * F_IN);
    const int L = out_size / (2 * B);

    static int smem_set = 0;
    if (!smem_set) {
        cudaFuncSetAttribute(lstm_mma_step, cudaFuncAttributeMaxDynamicSharedMemorySize, SM_TOTAL);
        smem_set = 1;
    }

    init_kernel<<<2048, 256>>>(Ws_hh, Wp_hh, Wd_hh);

    dim3 gs(HID / 32, B / 256, 2);
    for (int t = 0; t < T; t++) {
        StepParams p;
        p.xA = speed; p.xB = pos;
        p.x_stride = T * F_IN; p.x_off = t * F_IN;
        p.WihA = Ws_ih; p.WihB = Wp_ih;
        p.bihA = bs_ih; p.bihB = bp_ih;
        p.bhhA = bs_hh; p.bhhB = bp_hh;
        p.wsel = 0; p.ping = t & 1; p.is_dec = 0;
        lstm_mma_step<<<gs, 512, SM_TOTAL>>>(p);
    }

    int final_ping = ((T - 1) & 1) ^ 1;
    int n = B * HID;
    combine_kernel<<<(n + 255) / 256, 256>>>(final_ping, n);

    dim3 gd(HID / 32, B / 256, 1);
    for (int t = 0; t < L; t++) {
        StepParams p;
        if (t == 0) {
            p.xA = pos; p.xB = pos;
            p.x_stride = T * F_IN; p.x_off = (T - 1) * F_IN;
        } else {
            p.xA = nullptr; p.xB = nullptr;
            p.x_stride = F_IN; p.x_off = 0;
        }
        p.WihA = Wd_ih; p.WihB = Wd_ih;
        p.bihA = bd_ih; p.bihB = bd_ih;
        p.bhhA = bd_hh; p.bhhB = bd_hh;
        p.wsel = 2; p.ping = t & 1; p.is_dec = 1;
        lstm_mma_step<<<gd, 512, SM_TOTAL>>>(p);

        fc_kernel<<<(B + 7) / 8, 256>>>(W_fc, b_fc, W_emb, b_emb,
                                        out, (t + 1) & 1, t, L, B);
    }
}

// round 5
// speedup vs baseline: 10.5349x; 1.1450x over previous
#include <cuda_runtime.h>
#include <cuda_bf16.h>
#include <math.h>
#include <stdint.h>

// ---------------------------------------------------------------------------
// Intention_PS_LSTM on GB300 (sm_103 target -> mma.sync bf16 HMMA path).
// gates[8192,2048] = h[8192,512] @ Whh^T, per CTA: M=256, N=128(4g x 32u), K=512.
// bf16 weights/h, fp32 accum + fp32 cell state. 3-stage cp.async pipeline.
// Round 5: tanh.approx.f32 activations (1 MUFU vs ~20-instr tanhf polynomial).
// ---------------------------------------------------------------------------

#define HID   512
#define F_IN  4
#define MAXB  8192
#define BH    ((size_t)MAXB * HID)
#define WSZ   (4 * HID * HID)          // one Whh: 2048*512

#define SWZ(x) ((x) ^ ((((uint32_t)(x)) >> 3) & 0x70))

// smem byte offsets
#define SM_WX     0                    // float4[128]  = 2048
#define SM_BS     2048                 // float[128]   = 512
#define SM_XS     2560                 // float4[256]  = 4096
#define SM_A(s)   (8192 + (s) * 32768)     // 256 x 128B per stage
#define SM_B(s)   (106496 + (s) * 16384)   // 128 x 128B per stage
#define SM_TOTAL  155648

__device__ __align__(16) __nv_bfloat16 g_wb[3 * WSZ];   // bf16 Whh: s,p,d
__device__ __align__(16) __nv_bfloat16 g_h[4 * BH];     // encoder h: ping*2+z
__device__ __align__(16) float         g_c[2 * BH];     // encoder c: z
__device__ __align__(16) __nv_bfloat16 g_hd[2 * BH];    // decoder h ping-pong
__device__ __align__(16) float         g_cd[BH];        // decoder c
__device__ __align__(16) float         g_lastpos[MAXB * F_IN];

__device__ __forceinline__ float tanh_f(float x) {
    float y;
    asm("tanh.approx.f32 %0, %1;" : "=f"(y) : "f"(x));
    return y;
}
__device__ __forceinline__ float sigm_(float x) {
    return fmaf(tanh_f(0.5f * x), 0.5f, 0.5f);
}

__device__ __forceinline__ uint32_t smem_u32(const void* p) {
    uint32_t a;
    asm("{ .reg .u64 t; cvta.to.shared.u64 t, %1; cvt.u32.u64 %0, t; }" : "=r"(a) : "l"(p));
    return a;
}
__device__ __forceinline__ void cp16(uint32_t s, const void* g) {
    asm volatile("cp.async.cg.shared.global [%0], [%1], 16;" :: "r"(s), "l"(g));
}
#define CP_COMMIT() asm volatile("cp.async.commit_group;" ::: "memory")
#define CP_WAIT1()  asm volatile("cp.async.wait_group 1;" ::: "memory")
#define CP_WAIT0()  asm volatile("cp.async.wait_group 0;" ::: "memory")

__device__ __forceinline__ void ldsm4(uint32_t* r, uint32_t addr) {
    asm volatile("ldmatrix.sync.aligned.m8n8.x4.shared.b16 {%0,%1,%2,%3}, [%4];"
                 : "=r"(r[0]), "=r"(r[1]), "=r"(r[2]), "=r"(r[3]) : "r"(addr));
}
__device__ __forceinline__ void mma_bf16(float* d, const uint32_t* a, const uint32_t* b) {
    asm volatile("mma.sync.aligned.m16n8k16.row.col.f32.bf16.bf16.f32 "
                 "{%0,%1,%2,%3}, {%4,%5,%6,%7}, {%8,%9}, {%0,%1,%2,%3};"
                 : "+f"(d[0]), "+f"(d[1]), "+f"(d[2]), "+f"(d[3])
                 : "r"(a[0]), "r"(a[1]), "r"(a[2]), "r"(a[3]), "r"(b[0]), "r"(b[1]));
}

// ---------------------------------------------------------------------------
__global__ void init_kernel(const float* __restrict__ ws,
                            const float* __restrict__ wp,
                            const float* __restrict__ wd)
{
    size_t i = (size_t)blockIdx.x * blockDim.x + threadIdx.x;
    size_t stride = (size_t)gridDim.x * blockDim.x;
    for (size_t k = i; k < 3 * (size_t)WSZ; k += stride) {
        size_t w = k / WSZ, r = k % WSZ;
        const float* src = (w == 0) ? ws : (w == 1) ? wp : wd;
        g_wb[k] = __float2bfloat16(src[r]);
    }
    for (size_t k = i; k < 2 * BH; k += stride) {
        g_h[k] = __float2bfloat16(0.f);
        g_c[k] = 0.f;
    }
}

// ---------------------------------------------------------------------------
struct StepParams {
    const float* xA; const float* xB;   // per-z input; NULL => g_lastpos
    int x_stride; int x_off;
    const float* WihA; const float* WihB;
    const float* bihA; const float* bihB;
    const float* bhhA; const float* bhhB;
    int wsel;                           // Whh base: encoder 0 (+z), decoder 2
    int ping; int is_dec;
};

__device__ __forceinline__ void load_chunk(uint32_t Ab, uint32_t Bb,
                                           const __nv_bfloat16* __restrict__ hin,
                                           const __nv_bfloat16* __restrict__ Whh,
                                           int m_base, int jbase, int kf, int tid)
{
    #pragma unroll
    for (int it = 0; it < 4; it++) {                    // A: 256 rows x 8 x 16B
        int idx = tid + it * 512;
        int row = idx >> 3, c16 = idx & 7;
        cp16(Ab + SWZ(row * 128 + c16 * 16),
             hin + (size_t)(m_base + row) * HID + kf + c16 * 8);
    }
    #pragma unroll
    for (int it = 0; it < 2; it++) {                    // B: 128 rows x 8 x 16B
        int idx = tid + it * 512;
        int row = idx >> 3, c16 = idx & 7;
        int g = row >> 5, jj = row & 31;
        cp16(Bb + SWZ(row * 128 + c16 * 16),
             Whh + (size_t)(g * HID + jbase + jj) * HID + kf + c16 * 8);
    }
}

__global__ __launch_bounds__(512, 1) void lstm_mma_step(StepParams p)
{
    extern __shared__ char smem[];
    const uint32_t sb = smem_u32(smem);
    const int tid  = threadIdx.x;
    const int wid  = tid >> 5, lane = tid & 31;
    const int z    = blockIdx.z;
    const int warp_m = wid & 3;        // 4 m-groups of 64 rows
    const int warp_n = wid >> 2;       // 4 n-groups of 8 units

    const float* __restrict__ Wih = z ? p.WihB : p.WihA;
    const float* __restrict__ bih = z ? p.bihB : p.bihA;
    const float* __restrict__ bhh = z ? p.bhhB : p.bhhA;
    const float* __restrict__ xin = z ? p.xB : p.xA;
    const __nv_bfloat16* __restrict__ Whh = g_wb + (size_t)(p.wsel + z) * WSZ;

    const __nv_bfloat16* __restrict__ hin;
    __nv_bfloat16* __restrict__ hout;
    float* __restrict__ cio;
    if (p.is_dec) {
        hin  = g_hd + (size_t)p.ping * BH;
        hout = g_hd + (size_t)(p.ping ^ 1) * BH;
        cio  = g_cd;
        if (!xin) xin = g_lastpos;
    } else {
        hin  = g_h + (size_t)(p.ping * 2 + z) * BH;
        hout = g_h + (size_t)((p.ping ^ 1) * 2 + z) * BH;
        cio  = g_c + (size_t)z * BH;
    }

    const int m_base = blockIdx.y * 256;
    const int jbase  = blockIdx.x * 32;

    float4* Wx = (float4*)(smem + SM_WX);
    float*  Bs = (float*)(smem + SM_BS);
    float4* Xs = (float4*)(smem + SM_XS);

    if (tid < 128) {
        int g = tid >> 5, u = tid & 31;
        int gr = g * HID + jbase + u;
        Bs[tid] = bih[gr] + bhh[gr];
        Wx[tid] = *(const float4*)(Wih + (size_t)gr * F_IN);
    } else if (tid < 384) {
        int r = tid - 128;
        Xs[r] = *(const float4*)(xin + (size_t)(m_base + r) * p.x_stride + p.x_off);
    }

    // ldmatrix lane addressing
    const int perm  = (lane & 7) << 4;
    const int arow  = warp_m * 64 + (lane & 7) + ((lane >> 3) & 1) * 8;   // + mt*16
    const int koffA = ((lane >> 4) & 1) << 4;                             // + q*32
    const int brow0 = ((lane >> 4) & 1) * 32 + warp_n * 8 + (lane & 7);   // gates 0/1
    const int koffB = ((lane >> 3) & 1) << 4;

    float acc[4][4][4];   // [mt][gate][c]
    #pragma unroll
    for (int mt = 0; mt < 4; mt++)
        #pragma unroll
        for (int g = 0; g < 4; g++)
            #pragma unroll
            for (int c = 0; c < 4; c++) acc[mt][g][c] = 0.f;

    // prologue: prefetch chunks 0,1 into stages 0,1
    load_chunk(sb + SM_A(0), sb + SM_B(0), hin, Whh, m_base, jbase, 0, tid);  CP_COMMIT();
    load_chunk(sb + SM_A(1), sb + SM_B(1), hin, Whh, m_base, jbase, 64, tid); CP_COMMIT();

    for (int kc = 0; kc < 8; kc++) {
        if (kc == 7) { CP_WAIT0(); } else { CP_WAIT1(); }
        __syncthreads();

        // prefetch chunk kc+2 into the stage freed at the barrier above
        if (kc + 2 < 8) {
            int s = (kc + 2) % 3;
            load_chunk(sb + SM_A(s), sb + SM_B(s), hin, Whh,
                       m_base, jbase, (kc + 2) * 64, tid);
            CP_COMMIT();
        }

        const uint32_t Ab = sb + SM_A(kc % 3);
        const uint32_t Bb = sb + SM_B(kc % 3);

        #pragma unroll
        for (int q = 0; q < 4; q++) {            // 4 x k16 per chunk
            const int kq = q * 32;
            // B fragments first (2 ldsm4 -> 4 gates)
            uint32_t bf[4][2];
            {
                uint32_t r[4];
                ldsm4(r, Bb + brow0 * 128 + ((kq + koffB) ^ perm));
                bf[0][0] = r[0]; bf[0][1] = r[1]; bf[1][0] = r[2]; bf[1][1] = r[3];
                ldsm4(r, Bb + (brow0 + 64) * 128 + ((kq + koffB) ^ perm));
                bf[2][0] = r[0]; bf[2][1] = r[1]; bf[3][0] = r[2]; bf[3][1] = r[3];
            }
            uint32_t af[4][4];
            #pragma unroll
            for (int mt = 0; mt < 4; mt++)
                ldsm4(af[mt], Ab + (arow + mt * 16) * 128 + ((kq + koffA) ^ perm));

            #pragma unroll
            for (int mt = 0; mt < 4; mt++)
                #pragma unroll
                for (int g = 0; g < 4; g++)
                    mma_bf16(acc[mt][g], af[mt], bf[g]);
        }
    }

    // ---------------- fused epilogue (MUFU.TANH activations) ----------------
    const int l2 = lane >> 2;
    const int u0 = warp_n * 8 + (lane & 3) * 2;

    #pragma unroll
    for (int mt = 0; mt < 4; mt++) {
        #pragma unroll
        for (int rh = 0; rh < 2; rh++) {
            const int mloc = warp_m * 64 + mt * 16 + l2 + rh * 8;
            const int m = m_base + mloc;
            const float4 xv = Xs[mloc];
            const size_t base = (size_t)m * HID + jbase + u0;
            const float2 cold = *(const float2*)(cio + base);
            float hn[2], cn[2];
            #pragma unroll
            for (int e = 0; e < 2; e++) {
                const int u = u0 + e;
                const int ci = rh * 2 + e;
                float4 wi = Wx[u], wf = Wx[32 + u], wg = Wx[64 + u], wo = Wx[96 + u];
                float pi = acc[mt][0][ci] + Bs[u]      + wi.x*xv.x + wi.y*xv.y + wi.z*xv.z + wi.w*xv.w;
                float pf = acc[mt][1][ci] + Bs[32 + u] + wf.x*xv.x + wf.y*xv.y + wf.z*xv.z + wf.w*xv.w;
                float pg = acc[mt][2][ci] + Bs[64 + u] + wg.x*xv.x + wg.y*xv.y + wg.z*xv.z + wg.w*xv.w;
                float po = acc[mt][3][ci] + Bs[96 + u] + wo.x*xv.x + wo.y*xv.y + wo.z*xv.z + wo.w*xv.w;
                float ig = sigm_(pi), fg = sigm_(pf);
                float gg = tanh_f(pg), og = sigm_(po);
                float cc = fg * ((e == 0) ? cold.x : cold.y) + ig * gg;
                cn[e] = cc;
                hn[e] = og * tanh_f(cc);
            }
            *(float2*)(cio + base) = make_float2(cn[0], cn[1]);
            *(__nv_bfloat162*)(hout + base) =
                __nv_bfloat162(__float2bfloat16(hn[0]), __float2bfloat16(hn[1]));
        }
    }
}

// ---------------------------------------------------------------------------
__global__ void combine_kernel(int fp, int n)
{
    int i = blockIdx.x * blockDim.x + threadIdx.x;
    if (i < n) {
        float ha = __bfloat162float(g_h[(size_t)(fp * 2 + 0) * BH + i]);
        float hb = __bfloat162float(g_h[(size_t)(fp * 2 + 1) * BH + i]);
        g_hd[i] = __float2bfloat16(ha + hb);
        g_cd[i] = g_c[i] + g_c[BH + i];
    }
}

// ---------------------------------------------------------------------------
__global__ __launch_bounds__(256) void fc_kernel(
    const float* __restrict__ Wfc, const float* __restrict__ bfc,
    const float* __restrict__ Wemb, const float* __restrict__ bemb,
    float* __restrict__ out, int hping, int t, int L, int B)
{
    __shared__ float Wf[2 * HID];
    int tid = threadIdx.x;
    for (int i = tid; i < 2 * HID; i += 256) Wf[i] = Wfc[i];
    __syncthreads();

    int warp = tid >> 5, lane = tid & 31;
    int b = blockIdx.x * 8 + warp;
    if (b >= B) return;

    const __nv_bfloat16* hr = g_hd + (size_t)hping * BH + (size_t)b * HID;
    float s0 = 0.f, s1 = 0.f;
    #pragma unroll
    for (int k = lane; k < HID; k += 32) {
        float hv = __bfloat162float(hr[k]);
        s0 += hv * Wf[k];
        s1 += hv * Wf[HID + k];
    }
    #pragma unroll
    for (int o = 16; o; o >>= 1) {
        s0 += __shfl_xor_sync(0xFFFFFFFFu, s0, o);
        s1 += __shfl_xor_sync(0xFFFFFFFFu, s1, o);
    }
    if (lane == 0) {
        float c0 = fmaxf(s0 + bfc[0], 0.f);
        float c1 = fmaxf(s1 + bfc[1], 0.f);
        #pragma unroll
        for (int k = 0; k < 4; k++)
            g_lastpos[b * 4 + k] = fmaxf(c0 * Wemb[k * 2 + 0] + c1 * Wemb[k * 2 + 1] + bemb[k], 0.f);
        float mx = fmaxf(c0, c1);
        float e0 = __expf(c0 - mx), e1 = __expf(c1 - mx);
        float inv = 1.f / (e0 + e1);
        out[(size_t)b * L * 2 + t * 2 + 0] = e0 * inv;
        out[(size_t)b * L * 2 + t * 2 + 1] = e1 * inv;
    }
}

// ---------------------------------------------------------------------------
extern "C" void kernel_launch(void* const* d_in, const int* in_sizes, int n_in,
                              void* d_out, int out_size)
{
    const float* speed = (const float*)d_in[0];
    const float* pos   = (const float*)d_in[1];
    const float* Ws_ih = (const float*)d_in[2];
    const float* Ws_hh = (const float*)d_in[3];
    const float* bs_ih = (const float*)d_in[4];
    const float* bs_hh = (const float*)d_in[5];
    const float* Wp_ih = (const float*)d_in[6];
    const float* Wp_hh = (const float*)d_in[7];
    const float* bp_ih = (const float*)d_in[8];
    const float* bp_hh = (const float*)d_in[9];
    const float* Wd_ih = (const float*)d_in[10];
    const float* Wd_hh = (const float*)d_in[11];
    const float* bd_ih = (const float*)d_in[12];
    const float* bd_hh = (const float*)d_in[13];
    const float* W_fc  = (const float*)d_in[14];
    const float* b_fc  = (const float*)d_in[15];
    const float* W_emb = (const float*)d_in[16];
    const float* b_emb = (const float*)d_in[17];
    float* out = (float*)d_out;

    const int T = 16;
    const int B = in_sizes[0] / (T * F_IN);
    const int L = out_size / (2 * B);

    static int smem_set = 0;
    if (!smem_set) {
        cudaFuncSetAttribute(lstm_mma_step, cudaFuncAttributeMaxDynamicSharedMemorySize, SM_TOTAL);
        smem_set = 1;
    }

    init_kernel<<<2048, 256>>>(Ws_hh, Wp_hh, Wd_hh);

    dim3 gs(HID / 32, B / 256, 2);
    for (int t = 0; t < T; t++) {
        StepParams p;
        p.xA = speed; p.xB = pos;
        p.x_stride = T * F_IN; p.x_off = t * F_IN;
        p.WihA = Ws_ih; p.WihB = Wp_ih;
        p.bihA = bs_ih; p.bihB = bp_ih;
        p.bhhA = bs_hh; p.bhhB = bp_hh;
        p.wsel = 0; p.ping = t & 1; p.is_dec = 0;
        lstm_mma_step<<<gs, 512, SM_TOTAL>>>(p);
    }

    int final_ping = ((T - 1) & 1) ^ 1;
    int n = B * HID;
    combine_kernel<<<(n + 255) / 256, 256>>>(final_ping, n);

    dim3 gd(HID / 32, B / 256, 1);
    for (int t = 0; t < L; t++) {
        StepParams p;
        if (t == 0) {
            p.xA = pos; p.xB = pos;
            p.x_stride = T * F_IN; p.x_off = (T - 1) * F_IN;
        } else {
            p.xA = nullptr; p.xB = nullptr;
            p.x_stride = F_IN; p.x_off = 0;
        }
        p.WihA = Wd_ih; p.WihB = Wd_ih;
        p.bihA = bd_ih; p.bihB = bd_ih;
        p.bhhA = bd_hh; p.bhhB = bd_hh;
        p.wsel = 2; p.ping = t & 1; p.is_dec = 1;
        lstm_mma_step<<<gd, 512, SM_TOTAL>>>(p);

        fc_kernel<<<(B + 7) / 8, 256>>>(W_fc, b_fc, W_emb, b_emb,
                                        out, (t + 1) & 1, t, L, B);
    }
}

// round 8
// speedup vs baseline: 12.0987x; 1.1484x over previous
#include <cuda_runtime.h>
#include <cuda_bf16.h>
#include <math.h>
#include <stdint.h>

// ---------------------------------------------------------------------------
// Intention_PS_LSTM on GB300 (sm_103 target -> mma.sync bf16 HMMA path).
// gates[8192,2048] = h[8192,512] @ Whh^T, per CTA: M=128, N=128(4g x 32u), K=512.
// 256 threads, 2 CTAs/SM (regfile + smem sized to fit), 3-stage cp.async pipe.
// (Resubmission of round-6 kernel: previous bench was an infra failure.)
// ---------------------------------------------------------------------------

#define HID   512
#define F_IN  4
#define MAXB  8192
#define BH    ((size_t)MAXB * HID)
#define WSZ   (4 * HID * HID)          // one Whh: 2048*512

#define SWZ(x) ((x) ^ ((((uint32_t)(x)) >> 3) & 0x70))

// smem byte offsets (tiles 1024-aligned)
#define SM_WX     0                    // float4[128]  = 2048
#define SM_BS     2048                 // float[128]   = 512
#define SM_XS     2560                 // float4[128]  = 2048
#define SM_A(s)   (8192  + (s) * 16384)    // 128 x 128B per stage
#define SM_B(s)   (57344 + (s) * 16384)    // 128 x 128B per stage
#define SM_TOTAL  106496

__device__ __align__(16) __nv_bfloat16 g_wb[3 * WSZ];   // bf16 Whh: s,p,d
__device__ __align__(16) __nv_bfloat16 g_h[4 * BH];     // encoder h: ping*2+z
__device__ __align__(16) float         g_c[2 * BH];     // encoder c: z
__device__ __align__(16) __nv_bfloat16 g_hd[2 * BH];    // decoder h ping-pong
__device__ __align__(16) float         g_cd[BH];        // decoder c
__device__ __align__(16) float         g_lastpos[MAXB * F_IN];

__device__ __forceinline__ float tanh_f(float x) {
    float y;
    asm("tanh.approx.f32 %0, %1;" : "=f"(y) : "f"(x));
    return y;
}
__device__ __forceinline__ float sigm_(float x) {
    return fmaf(tanh_f(0.5f * x), 0.5f, 0.5f);
}

__device__ __forceinline__ uint32_t smem_u32(const void* p) {
    uint32_t a;
    asm("{ .reg .u64 t; cvta.to.shared.u64 t, %1; cvt.u32.u64 %0, t; }" : "=r"(a) : "l"(p));
    return a;
}
__device__ __forceinline__ void cp16(uint32_t s, const void* g) {
    asm volatile("cp.async.cg.shared.global [%0], [%1], 16;" :: "r"(s), "l"(g));
}
#define CP_COMMIT() asm volatile("cp.async.commit_group;" ::: "memory")
#define CP_WAIT1()  asm volatile("cp.async.wait_group 1;" ::: "memory")
#define CP_WAIT0()  asm volatile("cp.async.wait_group 0;" ::: "memory")

__device__ __forceinline__ void ldsm4(uint32_t* r, uint32_t addr) {
    asm volatile("ldmatrix.sync.aligned.m8n8.x4.shared.b16 {%0,%1,%2,%3}, [%4];"
                 : "=r"(r[0]), "=r"(r[1]), "=r"(r[2]), "=r"(r[3]) : "r"(addr));
}
__device__ __forceinline__ void mma_bf16(float* d, const uint32_t* a, const uint32_t* b) {
    asm volatile("mma.sync.aligned.m16n8k16.row.col.f32.bf16.bf16.f32 "
                 "{%0,%1,%2,%3}, {%4,%5,%6,%7}, {%8,%9}, {%0,%1,%2,%3};"
                 : "+f"(d[0]), "+f"(d[1]), "+f"(d[2]), "+f"(d[3])
                 : "r"(a[0]), "r"(a[1]), "r"(a[2]), "r"(a[3]), "r"(b[0]), "r"(b[1]));
}

// ---------------------------------------------------------------------------
__global__ void init_kernel(const float* __restrict__ ws,
                            const float* __restrict__ wp,
                            const float* __restrict__ wd)
{
    size_t i = (size_t)blockIdx.x * blockDim.x + threadIdx.x;
    size_t stride = (size_t)gridDim.x * blockDim.x;
    for (size_t k = i; k < 3 * (size_t)WSZ; k += stride) {
        size_t w = k / WSZ, r = k % WSZ;
        const float* src = (w == 0) ? ws : (w == 1) ? wp : wd;
        g_wb[k] = __float2bfloat16(src[r]);
    }
    for (size_t k = i; k < 2 * BH; k += stride) {
        g_h[k] = __float2bfloat16(0.f);
        g_c[k] = 0.f;
    }
}

// ---------------------------------------------------------------------------
struct StepParams {
    const float* xA; const float* xB;   // per-z input; NULL => g_lastpos
    int x_stride; int x_off;
    const float* WihA; const float* WihB;
    const float* bihA; const float* bihB;
    const float* bhhA; const float* bhhB;
    int wsel;                           // Whh base: encoder 0 (+z), decoder 2
    int ping; int is_dec;
};

__device__ __forceinline__ void load_chunk(uint32_t Ab, uint32_t Bb,
                                           const __nv_bfloat16* __restrict__ hin,
                                           const __nv_bfloat16* __restrict__ Whh,
                                           int m_base, int jbase, int kf, int tid)
{
    #pragma unroll
    for (int it = 0; it < 4; it++) {                    // A: 128 rows x 8 x 16B
        int idx = tid + it * 256;
        int row = idx >> 3, c16 = idx & 7;
        cp16(Ab + SWZ(row * 128 + c16 * 16),
             hin + (size_t)(m_base + row) * HID + kf + c16 * 8);
    }
    #pragma unroll
    for (int it = 0; it < 4; it++) {                    // B: 128 rows x 8 x 16B
        int idx = tid + it * 256;
        int row = idx >> 3, c16 = idx & 7;
        int g = row >> 5, jj = row & 31;
        cp16(Bb + SWZ(row * 128 + c16 * 16),
             Whh + (size_t)(g * HID + jbase + jj) * HID + kf + c16 * 8);
    }
}

__global__ __launch_bounds__(256, 2) void lstm_mma_step(StepParams p)
{
    extern __shared__ char smem[];
    const uint32_t sb = smem_u32(smem);
    const int tid  = threadIdx.x;
    const int wid  = tid >> 5, lane = tid & 31;
    const int z    = blockIdx.z;
    const int warp_m = wid & 1;        // 2 m-groups of 64 rows
    const int warp_n = wid >> 1;       // 4 n-groups of 8 units

    const float* __restrict__ Wih = z ? p.WihB : p.WihA;
    const float* __restrict__ bih = z ? p.bihB : p.bihA;
    const float* __restrict__ bhh = z ? p.bhhB : p.bhhA;
    const float* __restrict__ xin = z ? p.xB : p.xA;
    const __nv_bfloat16* __restrict__ Whh = g_wb + (size_t)(p.wsel + z) * WSZ;

    const __nv_bfloat16* __restrict__ hin;
    __nv_bfloat16* __restrict__ hout;
    float* __restrict__ cio;
    if (p.is_dec) {
        hin  = g_hd + (size_t)p.ping * BH;
        hout = g_hd + (size_t)(p.ping ^ 1) * BH;
        cio  = g_cd;
        if (!xin) xin = g_lastpos;
    } else {
        hin  = g_h + (size_t)(p.ping * 2 + z) * BH;
        hout = g_h + (size_t)((p.ping ^ 1) * 2 + z) * BH;
        cio  = g_c + (size_t)z * BH;
    }

    const int m_base = blockIdx.y * 128;
    const int jbase  = blockIdx.x * 32;

    float4* Wx = (float4*)(smem + SM_WX);
    float*  Bs = (float*)(smem + SM_BS);
    float4* Xs = (float4*)(smem + SM_XS);

    if (tid < 128) {
        int g = tid >> 5, u = tid & 31;
        int gr = g * HID + jbase + u;
        Bs[tid] = bih[gr] + bhh[gr];
        Wx[tid] = *(const float4*)(Wih + (size_t)gr * F_IN);
    } else {
        int r = tid - 128;
        Xs[r] = *(const float4*)(xin + (size_t)(m_base + r) * p.x_stride + p.x_off);
    }

    // ldmatrix lane addressing
    const int perm  = (lane & 7) << 4;
    const int arow  = warp_m * 64 + (lane & 7) + ((lane >> 3) & 1) * 8;   // + mt*16
    const int koffA = ((lane >> 4) & 1) << 4;                             // + q*32
    const int brow0 = ((lane >> 4) & 1) * 32 + warp_n * 8 + (lane & 7);   // gates 0/1
    const int koffB = ((lane >> 3) & 1) << 4;

    float acc[4][4][4];   // [mt][gate][c]
    #pragma unroll
    for (int mt = 0; mt < 4; mt++)
        #pragma unroll
        for (int g = 0; g < 4; g++)
            #pragma unroll
            for (int c = 0; c < 4; c++) acc[mt][g][c] = 0.f;

    // prologue: prefetch chunks 0,1 into stages 0,1
    load_chunk(sb + SM_A(0), sb + SM_B(0), hin, Whh, m_base, jbase, 0, tid);  CP_COMMIT();
    load_chunk(sb + SM_A(1), sb + SM_B(1), hin, Whh, m_base, jbase, 64, tid); CP_COMMIT();

    for (int kc = 0; kc < 8; kc++) {
        if (kc == 7) { CP_WAIT0(); } else { CP_WAIT1(); }
        __syncthreads();

        // prefetch chunk kc+2 into the stage freed at the barrier above
        if (kc + 2 < 8) {
            int s = (kc + 2) % 3;
            load_chunk(sb + SM_A(s), sb + SM_B(s), hin, Whh,
                       m_base, jbase, (kc + 2) * 64, tid);
            CP_COMMIT();
        }

        const uint32_t Ab = sb + SM_A(kc % 3);
        const uint32_t Bb = sb + SM_B(kc % 3);

        #pragma unroll
        for (int q = 0; q < 4; q++) {            // 4 x k16 per chunk
            const int kq = q * 32;
            uint32_t bf[4][2];
            {
                uint32_t r[4];
                ldsm4(r, Bb + brow0 * 128 + ((kq + koffB) ^ perm));
                bf[0][0] = r[0]; bf[0][1] = r[1]; bf[1][0] = r[2]; bf[1][1] = r[3];
                ldsm4(r, Bb + (brow0 + 64) * 128 + ((kq + koffB) ^ perm));
                bf[2][0] = r[0]; bf[2][1] = r[1]; bf[3][0] = r[2]; bf[3][1] = r[3];
            }
            uint32_t af[4][4];
            #pragma unroll
            for (int mt = 0; mt < 4; mt++)
                ldsm4(af[mt], Ab + (arow + mt * 16) * 128 + ((kq + koffA) ^ perm));

            #pragma unroll
            for (int mt = 0; mt < 4; mt++)
                #pragma unroll
                for (int g = 0; g < 4; g++)
                    mma_bf16(acc[mt][g], af[mt], bf[g]);
        }
    }

    // ---------------- fused epilogue (MUFU.TANH activations) ----------------
    const int l2 = lane >> 2;
    const int u0 = warp_n * 8 + (lane & 3) * 2;

    #pragma unroll
    for (int mt = 0; mt < 4; mt++) {
        #pragma unroll
        for (int rh = 0; rh < 2; rh++) {
            const int mloc = warp_m * 64 + mt * 16 + l2 + rh * 8;
            const int m = m_base + mloc;
            const float4 xv = Xs[mloc];
            const size_t base = (size_t)m * HID + jbase + u0;
            const float2 cold = *(const float2*)(cio + base);
            float hn[2], cn[2];
            #pragma unroll
            for (int e = 0; e < 2; e++) {
                const int u = u0 + e;
                const int ci = rh * 2 + e;
                float4 wi = Wx[u], wf = Wx[32 + u], wg = Wx[64 + u], wo = Wx[96 + u];
                float pi = acc[mt][0][ci] + Bs[u]      + wi.x*xv.x + wi.y*xv.y + wi.z*xv.z + wi.w*xv.w;
                float pf = acc[mt][1][ci] + Bs[32 + u] + wf.x*xv.x + wf.y*xv.y + wf.z*xv.z + wf.w*xv.w;
                float pg = acc[mt][2][ci] + Bs[64 + u] + wg.x*xv.x + wg.y*xv.y + wg.z*xv.z + wg.w*xv.w;
                float po = acc[mt][3][ci] + Bs[96 + u] + wo.x*xv.x + wo.y*xv.y + wo.z*xv.z + wo.w*xv.w;
                float ig = sigm_(pi), fg = sigm_(pf);
                float gg = tanh_f(pg), og = sigm_(po);
                float cc = fg * ((e == 0) ? cold.x : cold.y) + ig * gg;
                cn[e] = cc;
                hn[e] = og * tanh_f(cc);
            }
            *(float2*)(cio + base) = make_float2(cn[0], cn[1]);
            *(__nv_bfloat162*)(hout + base) =
                __nv_bfloat162(__float2bfloat16(hn[0]), __float2bfloat16(hn[1]));
        }
    }
}

// ---------------------------------------------------------------------------
__global__ void combine_kernel(int fp, int n)
{
    int i = blockIdx.x * blockDim.x + threadIdx.x;
    if (i < n) {
        float ha = __bfloat162float(g_h[(size_t)(fp * 2 + 0) * BH + i]);
        float hb = __bfloat162float(g_h[(size_t)(fp * 2 + 1) * BH + i]);
        g_hd[i] = __float2bfloat16(ha + hb);
        g_cd[i] = g_c[i] + g_c[BH + i];
    }
}

// ---------------------------------------------------------------------------
__global__ __launch_bounds__(256) void fc_kernel(
    const float* __restrict__ Wfc, const float* __restrict__ bfc,
    const float* __restrict__ Wemb, const float* __restrict__ bemb,
    float* __restrict__ out, int hping, int t, int L, int B)
{
    __shared__ float Wf[2 * HID];
    int tid = threadIdx.x;
    for (int i = tid; i < 2 * HID; i += 256) Wf[i] = Wfc[i];
    __syncthreads();

    int warp = tid >> 5, lane = tid & 31;
    int b = blockIdx.x * 8 + warp;
    if (b >= B) return;

    const __nv_bfloat16* hr = g_hd + (size_t)hping * BH + (size_t)b * HID;
    float s0 = 0.f, s1 = 0.f;
    #pragma unroll
    for (int k = lane; k < HID; k += 32) {
        float hv = __bfloat162float(hr[k]);
        s0 += hv * Wf[k];
        s1 += hv * Wf[HID + k];
    }
    #pragma unroll
    for (int o = 16; o; o >>= 1) {
        s0 += __shfl_xor_sync(0xFFFFFFFFu, s0, o);
        s1 += __shfl_xor_sync(0xFFFFFFFFu, s1, o);
    }
    if (lane == 0) {
        float c0 = fmaxf(s0 + bfc[0], 0.f);
        float c1 = fmaxf(s1 + bfc[1], 0.f);
        #pragma unroll
        for (int k = 0; k < 4; k++)
            g_lastpos[b * 4 + k] = fmaxf(c0 * Wemb[k * 2 + 0] + c1 * Wemb[k * 2 + 1] + bemb[k], 0.f);
        float mx = fmaxf(c0, c1);
        float e0 = __expf(c0 - mx), e1 = __expf(c1 - mx);
        float inv = 1.f / (e0 + e1);
        out[(size_t)b * L * 2 + t * 2 + 0] = e0 * inv;
        out[(size_t)b * L * 2 + t * 2 + 1] = e1 * inv;
    }
}

// ---------------------------------------------------------------------------
extern "C" void kernel_launch(void* const* d_in, const int* in_sizes, int n_in,
                              void* d_out, int out_size)
{
    const float* speed = (const float*)d_in[0];
    const float* pos   = (const float*)d_in[1];
    const float* Ws_ih = (const float*)d_in[2];
    const float* Ws_hh = (const float*)d_in[3];
    const float* bs_ih = (const float*)d_in[4];
    const float* bs_hh = (const float*)d_in[5];
    const float* Wp_ih = (const float*)d_in[6];
    const float* Wp_hh = (const float*)d_in[7];
    const float* bp_ih = (const float*)d_in[8];
    const float* bp_hh = (const float*)d_in[9];
    const float* Wd_ih = (const float*)d_in[10];
    const float* Wd_hh = (const float*)d_in[11];
    const float* bd_ih = (const float*)d_in[12];
    const float* bd_hh = (const float*)d_in[13];
    const float* W_fc  = (const float*)d_in[14];
    const float* b_fc  = (const float*)d_in[15];
    const float* W_emb = (const float*)d_in[16];
    const float* b_emb = (const float*)d_in[17];
    float* out = (float*)d_out;

    const int T = 16;
    const int B = in_sizes[0] / (T * F_IN);
    const int L = out_size / (2 * B);

    static int smem_set = 0;
    if (!smem_set) {
        cudaFuncSetAttribute(lstm_mma_step, cudaFuncAttributeMaxDynamicSharedMemorySize, SM_TOTAL);
        smem_set = 1;
    }

    init_kernel<<<2048, 256>>>(Ws_hh, Wp_hh, Wd_hh);

    dim3 gs(HID / 32, B / 128, 2);
    for (int t = 0; t < T; t++) {
        StepParams p;
        p.xA = speed; p.xB = pos;
        p.x_stride = T * F_IN; p.x_off = t * F_IN;
        p.WihA = Ws_ih; p.WihB = Wp_ih;
        p.bihA = bs_ih; p.bihB = bp_ih;
        p.bhhA = bs_hh; p.bhhB = bp_hh;
        p.wsel = 0; p.ping = t & 1; p.is_dec = 0;
        lstm_mma_step<<<gs, 256, SM_TOTAL>>>(p);
    }

    int final_ping = ((T - 1) & 1) ^ 1;
    int n = B * HID;
    combine_kernel<<<(n + 255) / 256, 256>>>(final_ping, n);

    dim3 gd(HID / 32, B / 128, 1);
    for (int t = 0; t < L; t++) {
        StepParams p;
        if (t == 0) {
            p.xA = pos; p.xB = pos;
            p.x_stride = T * F_IN; p.x_off = (T - 1) * F_IN;
        } else {
            p.xA = nullptr; p.xB = nullptr;
            p.x_stride = F_IN; p.x_off = 0;
        }
        p.WihA = Wd_ih; p.WihB = Wd_ih;
        p.bihA = bd_ih; p.bihB = bd_ih;
        p.bhhA = bd_hh; p.bhhB = bd_hh;
        p.wsel = 2; p.ping = t & 1; p.is_dec = 1;
        lstm_mma_step<<<gd, 256, SM_TOTAL>>>(p);

        fc_kernel<<<(B + 7) / 8, 256>>>(W_fc, b_fc, W_emb, b_emb,
                                        out, (t + 1) & 1, t, L, B);
    }
}